// round 6
// baseline (speedup 1.0000x reference)
#include <cuda_runtime.h>
#include <cuda_bf16.h>
#include <cstdint>

// GraphSAGE on GB300 via mma.sync bf16 hi/lo (3-MMA fp32 emulation).
// R6: CTA 64x128, gather issue/consume interleaved with MMA blocks so the
// neighbor-load latency is bridged by the same warp's MMAs. adj hoisted.

#define N_NODES 100000
#define DIM     256
#define KDIM    512
#define NNEIGH  10
#define BM      64
#define BN      128
#define KC      32
#define NCHUNK  16
#define THREADS 256

// smem (bytes): A double buffer then W double buffer
#define ABUF    8192             // 64 rows x 128B (hi 64B | lo 64B)
#define WBASE   16384
#define WBUF    16384            // per W buffer: hi 8K + lo 8K
#define W_LO    8192
#define SMEM_TOTAL (WBASE + 2 * WBUF)   // 49152

__device__ float g_buf0[(size_t)N_NODES * DIM];
__device__ float g_buf1[(size_t)N_NODES * DIM];
// W fragments: [layer][half][chunk][hi/lo][ [kt(2)][nt_local(16)][lane(32)][2] u32 ]
__device__ uint32_t g_wfrag[3][2][16][2][2048];

__device__ __forceinline__ uint32_t smem_u32(const void* p) {
    uint32_t a;
    asm("{ .reg .u64 t; cvta.to.shared.u64 t, %1; cvt.u32.u64 %0, t; }" : "=r"(a) : "l"(p));
    return a;
}
__device__ __forceinline__ uint32_t sw128(uint32_t off) {
    return off ^ ((off >> 3) & 0x70);
}
__device__ __forceinline__ uint32_t pack_bf2(float a, float b) {
    __nv_bfloat162 t = __floats2bfloat162_rn(a, b);
    return *reinterpret_cast<uint32_t*>(&t);
}
__device__ __forceinline__ void ldmat4(uint32_t* r, uint32_t addr) {
    asm volatile("ldmatrix.sync.aligned.m8n8.x4.shared.b16 {%0,%1,%2,%3}, [%4];"
                 : "=r"(r[0]), "=r"(r[1]), "=r"(r[2]), "=r"(r[3]) : "r"(addr));
}
__device__ __forceinline__ void mma16816(float* c, const uint32_t* a, uint32_t b0, uint32_t b1) {
    asm volatile("mma.sync.aligned.m16n8k16.row.col.f32.bf16.bf16.f32 "
                 "{%0,%1,%2,%3}, {%4,%5,%6,%7}, {%8,%9}, {%0,%1,%2,%3};"
                 : "+f"(c[0]), "+f"(c[1]), "+f"(c[2]), "+f"(c[3])
                 : "r"(a[0]), "r"(a[1]), "r"(a[2]), "r"(a[3]), "r"(b0), "r"(b1));
}
__device__ __forceinline__ void cpasync16(uint32_t smem_dst, const void* gsrc) {
    asm volatile("cp.async.cg.shared.global [%0], [%1], 16;"
                 :: "r"(smem_dst), "l"(gsrc) : "memory");
}
__device__ __forceinline__ void cpasync_commit() {
    asm volatile("cp.async.commit_group;" ::: "memory");
}
__device__ __forceinline__ void cpasync_wait0() {
    asm volatile("cp.async.wait_group 0;" ::: "memory");
}

// -------- W prep: hi/lo split, per-(half,chunk) 16KB slabs in B-frag order ----
__global__ void prep_wfrag(const float* __restrict__ W0, const float* __restrict__ W1,
                           const float* __restrict__ W2)
{
    int idx = blockIdx.x * blockDim.x + threadIdx.x;
    if (idx >= 3 * 2 * 16 * 2 * 16 * 32) return;    // 98304
    const int lane  = idx & 31;
    const int ntl   = (idx >> 5) & 15;
    const int kt    = (idx >> 9) & 1;
    const int kc    = (idx >> 10) & 15;
    const int half  = (idx >> 14) & 1;
    const int layer = idx >> 15;
    const float* W = layer == 0 ? W0 : (layer == 1 ? W1 : W2);
    const int k0 = (kc * 2 + kt) * 16 + (lane & 3) * 2;
    const int n  = half * 128 + ntl * 8 + (lane >> 2);

    float v[4] = { W[(k0 + 0) * DIM + n], W[(k0 + 1) * DIM + n],
                   W[(k0 + 8) * DIM + n], W[(k0 + 9) * DIM + n] };
    float hi[4], lo[4];
    #pragma unroll
    for (int i = 0; i < 4; ++i) {
        __nv_bfloat16 h = __float2bfloat16(v[i]);
        hi[i] = __bfloat162float(h);
        lo[i] = v[i] - hi[i];
    }
    const int base = ((kt * 16 + ntl) * 32 + lane) * 2;
    g_wfrag[layer][half][kc][0][base + 0] = pack_bf2(hi[0], hi[1]);
    g_wfrag[layer][half][kc][0][base + 1] = pack_bf2(hi[2], hi[3]);
    g_wfrag[layer][half][kc][1][base + 0] = pack_bf2(lo[0], lo[1]);
    g_wfrag[layer][half][kc][1][base + 1] = pack_bf2(lo[2], lo[3]);
}

// -------- fused SAGE layer --------
template <bool RELU>
__global__ __launch_bounds__(THREADS, 2)
void sage_mma(const float* __restrict__ hin, const int* __restrict__ adj,
              const uint32_t* __restrict__ wf_layer,
              const float* __restrict__ bias, float* __restrict__ hout)
{
    extern __shared__ char smem[];
    const uint32_t sb = smem_u32(smem);
    const int tid  = threadIdx.x;
    const int lane = tid & 31;
    const int wid  = tid >> 5;
    const int wm   = wid & 1;     // rows wm*32..+31
    const int wn   = wid >> 1;    // cols wn*32..+31 (within this half)
    const int row0 = blockIdx.x * BM;
    const int half = blockIdx.y;

    const uint32_t* wf = wf_layer + (size_t)half * (16 * 4096);

    const int pr = tid >> 2;         // producer row 0..63
    const int pq = tid & 3;          // 8-col slice of the 32-col chunk
    const int prow = row0 + pr;
    const bool pvalid = prow < N_NODES;

    int adjreg[NNEIGH];
    #pragma unroll
    for (int j = 0; j < NNEIGH; ++j)
        adjreg[j] = pvalid ? adj[(size_t)prow * NNEIGH + j] : 0;

    float c[2][4][4];
    #pragma unroll
    for (int i = 0; i < 2; ++i)
        #pragma unroll
        for (int j = 0; j < 4; ++j)
            #pragma unroll
            for (int k = 0; k < 4; ++k) c[i][j][k] = 0.f;

    // ---- gather issue: raw float4 loads into rw ----
    auto issue = [&](int cc, int p, float4* rw) {
        const int col = (cc & 7) * KC + pq * 8 + p * 4;
        if (cc < 8) {
            if (pvalid) rw[0] = *(const float4*)(hin + (size_t)prow * DIM + col);
        } else if (pvalid) {
            #pragma unroll
            for (int j = 0; j < NNEIGH; ++j)
                rw[j] = *(const float4*)(hin + (size_t)adjreg[j] * DIM + col);
        }
    };
    // ---- gather consume: sum/mean, split hi/lo, store to A(cc) ----
    auto consume = [&](int cc, int p, const float4* rw) {
        float4 s = make_float4(0.f, 0.f, 0.f, 0.f);
        if (pvalid) {
            if (cc < 8) s = rw[0];
            else {
                #pragma unroll
                for (int j = 0; j < NNEIGH; ++j) {
                    s.x += rw[j].x; s.y += rw[j].y; s.z += rw[j].z; s.w += rw[j].w;
                }
                s.x *= 0.1f; s.y *= 0.1f; s.z *= 0.1f; s.w *= 0.1f;
            }
        }
        const __nv_bfloat16 hx = __float2bfloat16(s.x), hy = __float2bfloat16(s.y);
        const __nv_bfloat16 hz = __float2bfloat16(s.z), hw = __float2bfloat16(s.w);
        uint2 hv, lv;
        hv.x = pack_bf2(s.x, s.y);
        hv.y = pack_bf2(s.z, s.w);
        lv.x = pack_bf2(s.x - __bfloat162float(hx), s.y - __bfloat162float(hy));
        lv.y = pack_bf2(s.z - __bfloat162float(hz), s.w - __bfloat162float(hw));
        char* Ab = smem + (cc & 1) * ABUF;
        const uint32_t off = (uint32_t)(pr * 128 + pq * 16 + p * 8);
        *(uint2*)(Ab + sw128(off))      = hv;
        *(uint2*)(Ab + sw128(off + 64)) = lv;
    };
    // ---- W chunk slab copy (flat 16KB) ----
    auto wcopy = [&](int cc) {
        const uint32_t dst = sb + WBASE + (cc & 1) * WBUF;
        const uint4* src = (const uint4*)(wf + (size_t)cc * 4096);
        #pragma unroll
        for (int i = 0; i < 4; ++i) {
            const int e = tid + i * THREADS;    // 1024 uint4 total
            cpasync16(dst + e * 16, src + e);
        }
        cpasync_commit();
    };
    // ---- one kt sub-block: 24 MMAs ----
    auto mma_kt = [&](int kt, int kc) {
        const uint32_t Ab = sb + (kc & 1) * ABUF;
        const char*    Wp = smem + WBASE + (kc & 1) * WBUF;
        uint32_t ah0[4], ah1[4], al0[4], al1[4];
        const uint32_t off0 = (uint32_t)((wm * 32 + (lane & 15)) * 128 + kt * 32 + (lane >> 4) * 16);
        const uint32_t off1 = off0 + 16 * 128;
        ldmat4(ah0, Ab + sw128(off0));
        ldmat4(ah1, Ab + sw128(off1));
        ldmat4(al0, Ab + sw128(off0 + 64));
        ldmat4(al1, Ab + sw128(off1 + 64));

        const uint2* bhp = (const uint2*)(Wp + ((size_t)(kt * 16 + wn * 4) * 32 + lane) * 8);
        const uint2* blp = (const uint2*)(Wp + W_LO + ((size_t)(kt * 16 + wn * 4) * 32 + lane) * 8);
        uint2 b[4];
        #pragma unroll
        for (int nt = 0; nt < 4; ++nt) b[nt] = bhp[nt * 32];
        #pragma unroll
        for (int nt = 0; nt < 4; ++nt) {          // hh
            mma16816(c[0][nt], ah0, b[nt].x, b[nt].y);
            mma16816(c[1][nt], ah1, b[nt].x, b[nt].y);
        }
        #pragma unroll
        for (int nt = 0; nt < 4; ++nt) {          // lh
            mma16816(c[0][nt], al0, b[nt].x, b[nt].y);
            mma16816(c[1][nt], al1, b[nt].x, b[nt].y);
        }
        #pragma unroll
        for (int nt = 0; nt < 4; ++nt) b[nt] = blp[nt * 32];
        #pragma unroll
        for (int nt = 0; nt < 4; ++nt) {          // hl
            mma16816(c[0][nt], ah0, b[nt].x, b[nt].y);
            mma16816(c[1][nt], ah1, b[nt].x, b[nt].y);
        }
    };

    // ================= prologue =================
    wcopy(0);
    {
        float4 rw[NNEIGH];
        issue(0, 0, rw); consume(0, 0, rw);
        issue(0, 1, rw); consume(0, 1, rw);
    }
    cpasync_wait0();
    __syncthreads();

    // ================= main loop =================
    for (int kc = 0; kc < NCHUNK; ++kc) {
        const int cc = kc + 1;
        const bool nxt = cc < NCHUNK;
        if (nxt) wcopy(cc);

        float4 rw[NNEIGH];
        if (nxt) issue(cc, 0, rw);     // LDGs in flight across mma_kt(0)
        mma_kt(0, kc);
        if (nxt) { consume(cc, 0, rw); issue(cc, 1, rw); }
        mma_kt(1, kc);
        if (nxt) { consume(cc, 1, rw); cpasync_wait0(); }
        __syncthreads();
    }

    // ================= epilogue =================
    float2 bias2[4];
    #pragma unroll
    for (int nt = 0; nt < 4; ++nt)
        bias2[nt] = *(const float2*)&bias[half * 128 + wn * 32 + nt * 8 + (lane & 3) * 2];

    #pragma unroll
    for (int mt = 0; mt < 2; ++mt) {
        const int rbase = row0 + wm * 32 + mt * 16 + (lane >> 2);
        #pragma unroll
        for (int h = 0; h < 2; ++h) {
            const int row = rbase + h * 8;
            if (row < N_NODES) {
                #pragma unroll
                for (int nt = 0; nt < 4; ++nt) {
                    const int n = half * 128 + wn * 32 + nt * 8 + (lane & 3) * 2;
                    float2 o;
                    o.x = c[mt][nt][h * 2 + 0] + bias2[nt].x;
                    o.y = c[mt][nt][h * 2 + 1] + bias2[nt].y;
                    if (RELU) { o.x = fmaxf(o.x, 0.f); o.y = fmaxf(o.y, 0.f); }
                    *(float2*)(hout + (size_t)row * DIM + n) = o;
                }
            }
        }
    }
}

extern "C" void kernel_launch(void* const* d_in, const int* in_sizes, int n_in,
                              void* d_out, int out_size)
{
    const float* x   = (const float*)d_in[0];
    const int*   adj = (const int*)  d_in[1];
    const float* W0  = (const float*)d_in[2];
    const float* b0  = (const float*)d_in[3];
    const float* W1  = (const float*)d_in[4];
    const float* b1  = (const float*)d_in[5];
    const float* W2  = (const float*)d_in[6];
    const float* b2  = (const float*)d_in[7];
    float* out = (float*)d_out;

    void *p0, *p1, *pwf;
    cudaGetSymbolAddress(&p0, g_buf0);
    cudaGetSymbolAddress(&p1, g_buf1);
    cudaGetSymbolAddress(&pwf, g_wfrag);
    float* h1 = (float*)p0;
    float* h2 = (float*)p1;
    const uint32_t* wf = (const uint32_t*)pwf;
    const size_t WSZ = 2 * 16 * 2 * 2048;   // u32 per layer

    cudaFuncSetAttribute(sage_mma<true>,
                         cudaFuncAttributeMaxDynamicSharedMemorySize, SMEM_TOTAL);
    cudaFuncSetAttribute(sage_mma<false>,
                         cudaFuncAttributeMaxDynamicSharedMemorySize, SMEM_TOTAL);

    prep_wfrag<<<(3 * 2 * 16 * 2 * 16 * 32 + 255) / 256, 256>>>(W0, W1, W2);

    dim3 grid((N_NODES + BM - 1) / BM, 2);   // 1563 x 2
    sage_mma<true ><<<grid, THREADS, SMEM_TOTAL>>>(x,  adj, wf,           b0, h1);
    sage_mma<true ><<<grid, THREADS, SMEM_TOTAL>>>(h1, adj, wf + WSZ,     b1, h2);
    sage_mma<false><<<grid, THREADS, SMEM_TOTAL>>>(h2, adj, wf + 2 * WSZ, b2, out);
}